// round 4
// baseline (speedup 1.0000x reference)
#include <cuda_runtime.h>
#include <math.h>

#define B_ 16384
#define S_ 32
#define D_ 64
#define KTOP 3

constexpr int SD = S_ * D_;                      // 2048 floats per mem row
constexpr long long OFF_READ_R = 0;
constexpr long long OFF_READ_I = (long long)B_ * D_;                 // 1,048,576
constexpr long long OFF_NEXT_R = 2LL * B_ * D_;                      // 2,097,152
constexpr long long OFF_NEXT_I = OFF_NEXT_R + (long long)B_ * SD;    // 35,651,584
constexpr long long OFF_ENT    = OFF_NEXT_I + (long long)B_ * SD;    // 69,206,016

__global__ void am_init_kernel(float* __restrict__ out) {
    out[OFF_ENT] = 0.0f;
}

__global__ __launch_bounds__(256) void am_fused_kernel(
    const float* __restrict__ gw_r,  const float* __restrict__ gw_i,
    const float* __restrict__ mem_r, const float* __restrict__ mem_i,
    const float* __restrict__ Wg,    const float* __restrict__ bg,
    const float* __restrict__ Wa,    const float* __restrict__ ba,
    const float* __restrict__ gamma_r, const float* __restrict__ beta_r,
    const float* __restrict__ gamma_i, const float* __restrict__ beta_i,
    float* __restrict__ out)
{
    __shared__ float gwr[D_], gwi[D_];
    __shared__ float gr[D_], br[D_], gi[D_], bi[D_];
    __shared__ float sim[S_], logi[S_], attn[S_], sparse[S_];
    __shared__ float s_wg;
    __shared__ float pr[8][D_];   // per-warp partials for read_r
    __shared__ float pi_[8][D_];  // per-warp partials for read_i

    const int t    = threadIdx.x;
    const int b    = blockIdx.x;
    const int row  = t >> 3;      // slot 0..31
    const int q    = t & 7;       // column group
    const int d0   = q * 8;
    const int warp = t >> 5;
    const int lane = t & 31;
    const long long baseSD = (long long)b * SD;

    // ---- mem row -> registers (coalesced LDG.128, each thread owns 8 cols) ----
    const float4* pmr = (const float4*)(mem_r + baseSD + row * D_ + d0);
    const float4* pmi = (const float4*)(mem_i + baseSD + row * D_ + d0);
    const float4 r0 = pmr[0], r1 = pmr[1];
    const float4 i0 = pmi[0], i1 = pmi[1];

    // ---- Small per-row / constant vectors ----
    if (t < 64) {
        gwr[t] = gw_r[(long long)b * D_ + t];
        gr[t]  = gamma_r[t];
    } else if (t < 128) {
        const int d = t - 64;
        gwi[d] = gw_i[(long long)b * D_ + d];
        br[d]  = beta_r[d];
    } else if (t < 192) {
        gi[t - 128] = gamma_i[t - 128];
    } else {
        bi[t - 192] = beta_i[t - 192];
    }
    __syncthreads();

    // ---- sim[row] from registers: 8-lane partial + shfl reduce ----
    {
        float acc;
        acc = r0.x * gwr[d0 + 0];
        acc = fmaf(r0.y, gwr[d0 + 1], acc);
        acc = fmaf(r0.z, gwr[d0 + 2], acc);
        acc = fmaf(r0.w, gwr[d0 + 3], acc);
        acc = fmaf(r1.x, gwr[d0 + 4], acc);
        acc = fmaf(r1.y, gwr[d0 + 5], acc);
        acc = fmaf(r1.z, gwr[d0 + 6], acc);
        acc = fmaf(r1.w, gwr[d0 + 7], acc);
        acc = fmaf(i0.x, gwi[d0 + 0], acc);
        acc = fmaf(i0.y, gwi[d0 + 1], acc);
        acc = fmaf(i0.z, gwi[d0 + 2], acc);
        acc = fmaf(i0.w, gwi[d0 + 3], acc);
        acc = fmaf(i1.x, gwi[d0 + 4], acc);
        acc = fmaf(i1.y, gwi[d0 + 5], acc);
        acc = fmaf(i1.z, gwi[d0 + 6], acc);
        acc = fmaf(i1.w, gwi[d0 + 7], acc);
        acc += __shfl_xor_sync(0xffffffffu, acc, 4);
        acc += __shfl_xor_sync(0xffffffffu, acc, 2);
        acc += __shfl_xor_sync(0xffffffffu, acc, 1);
        if (q == 0) sim[row] = acc;

        // logits: flat = [gw_r, gw_i] (128), each of 8 subs handles 16 j's
        float lacc = 0.0f;
        const int j0 = q * 16;
        #pragma unroll
        for (int i = 0; i < 16; i++) {
            const int j = j0 + i;
            const float f = (j < 64) ? gwr[j] : gwi[j - 64];
            lacc = fmaf(f, Wa[j * S_ + row], lacc);
        }
        lacc += __shfl_xor_sync(0xffffffffu, lacc, 4);
        lacc += __shfl_xor_sync(0xffffffffu, lacc, 2);
        lacc += __shfl_xor_sync(0xffffffffu, lacc, 1);
        if (q == 0) logi[row] = lacc + ba[row];
    }
    __syncthreads();

    if (warp == 0) {
        // ---- attention softmax over S=32 ----
        const float v = sim[lane];
        float m = v;
        #pragma unroll
        for (int o = 16; o; o >>= 1) m = fmaxf(m, __shfl_xor_sync(0xffffffffu, m, o));
        const float e = __expf(v - m);
        float ssum = e;
        #pragma unroll
        for (int o = 16; o; o >>= 1) ssum += __shfl_xor_sync(0xffffffffu, ssum, o);
        attn[lane] = e / ssum;
    } else if (warp == 1) {
        // ---- write softmax, entropy, top-3 sparse ----
        const float v = logi[lane];
        float m = v;
        #pragma unroll
        for (int o = 16; o; o >>= 1) m = fmaxf(m, __shfl_xor_sync(0xffffffffu, m, o));
        const float e = __expf(v - m);
        float ssum = e;
        #pragma unroll
        for (int o = 16; o; o >>= 1) ssum += __shfl_xor_sync(0xffffffffu, ssum, o);
        const float w = e / ssum;

        float ent = -w * __logf(w + 1e-10f);
        #pragma unroll
        for (int o = 16; o; o >>= 1) ent += __shfl_xor_sync(0xffffffffu, ent, o);
        if (lane == 0) atomicAdd(out + OFF_ENT, ent * (1.0f / (float)B_));

        // top-3 via iterated butterfly argmax (tie -> lowest index)
        float vv = w;
        float sp = 0.0f;
        float sumTop = 0.0f;
        #pragma unroll
        for (int k = 0; k < KTOP; k++) {
            float mv = vv;
            int   mi = lane;
            #pragma unroll
            for (int o = 16; o; o >>= 1) {
                const float ov = __shfl_xor_sync(0xffffffffu, mv, o);
                const int   oi = __shfl_xor_sync(0xffffffffu, mi, o);
                if (ov > mv || (ov == mv && oi < mi)) { mv = ov; mi = oi; }
            }
            sumTop += mv;
            if (lane == mi) { sp = mv; vv = -INFINITY; }
        }
        sparse[lane] = sp / (sumTop + 1e-6f);
    } else if (warp == 2) {
        // ---- write gate ----
        float acc = 0.0f;
        #pragma unroll
        for (int i = 0; i < 4; i++) {
            const int j = lane + i * 32;
            const float f = (j < 64) ? gwr[j] : gwi[j - 64];
            acc = fmaf(f, Wg[j], acc);
        }
        #pragma unroll
        for (int o = 16; o; o >>= 1) acc += __shfl_xor_sync(0xffffffffu, acc, o);
        if (lane == 0) s_wg = 1.0f / (1.0f + __expf(-(acc + bg[0])));
    }
    __syncthreads();

    // ---- read-vector partials: scale regs by attn, fold 4 rows per warp ----
    {
        const float a = attn[row];
        float vr[8] = { a*r0.x, a*r0.y, a*r0.z, a*r0.w, a*r1.x, a*r1.y, a*r1.z, a*r1.w };
        float vi[8] = { a*i0.x, a*i0.y, a*i0.z, a*i0.w, a*i1.x, a*i1.y, a*i1.z, a*i1.w };
        #pragma unroll
        for (int i = 0; i < 8; i++) {
            vr[i] += __shfl_xor_sync(0xffffffffu, vr[i], 8);
            vr[i] += __shfl_xor_sync(0xffffffffu, vr[i], 16);
            vi[i] += __shfl_xor_sync(0xffffffffu, vi[i], 8);
            vi[i] += __shfl_xor_sync(0xffffffffu, vi[i], 16);
        }
        if (lane < 8) {   // lane == q, rows folded
            #pragma unroll
            for (int i = 0; i < 8; i++) {
                pr[warp][lane * 8 + i]  = vr[i];
                pi_[warp][lane * 8 + i] = vi[i];
            }
        }
    }

    // ---- memory update + LayerNorm from registers ----
    {
        const float eff = s_wg * sparse[row];
        const float om  = 1.0f - eff;

        float v[8];
        // real
        v[0] = om * r0.x + eff * gwr[d0 + 0];
        v[1] = om * r0.y + eff * gwr[d0 + 1];
        v[2] = om * r0.z + eff * gwr[d0 + 2];
        v[3] = om * r0.w + eff * gwr[d0 + 3];
        v[4] = om * r1.x + eff * gwr[d0 + 4];
        v[5] = om * r1.y + eff * gwr[d0 + 5];
        v[6] = om * r1.z + eff * gwr[d0 + 6];
        v[7] = om * r1.w + eff * gwr[d0 + 7];
        float sum = 0.0f, sq = 0.0f;
        #pragma unroll
        for (int i = 0; i < 8; i++) { sum += v[i]; sq = fmaf(v[i], v[i], sq); }
        sum += __shfl_xor_sync(0xffffffffu, sum, 4); sq += __shfl_xor_sync(0xffffffffu, sq, 4);
        sum += __shfl_xor_sync(0xffffffffu, sum, 2); sq += __shfl_xor_sync(0xffffffffu, sq, 2);
        sum += __shfl_xor_sync(0xffffffffu, sum, 1); sq += __shfl_xor_sync(0xffffffffu, sq, 1);
        float mean = sum * (1.0f / 64.0f);
        float var  = sq * (1.0f / 64.0f) - mean * mean;
        float rstd = rsqrtf(var + 1e-5f);
        {
            float o0[8];
            #pragma unroll
            for (int i = 0; i < 8; i++)
                o0[i] = fmaf((v[i] - mean) * rstd, gr[d0 + i], br[d0 + i]);
            float4* dst = (float4*)(out + OFF_NEXT_R + baseSD + row * D_ + d0);
            dst[0] = make_float4(o0[0], o0[1], o0[2], o0[3]);
            dst[1] = make_float4(o0[4], o0[5], o0[6], o0[7]);
        }
        // imag
        v[0] = om * i0.x + eff * gwi[d0 + 0];
        v[1] = om * i0.y + eff * gwi[d0 + 1];
        v[2] = om * i0.z + eff * gwi[d0 + 2];
        v[3] = om * i0.w + eff * gwi[d0 + 3];
        v[4] = om * i1.x + eff * gwi[d0 + 4];
        v[5] = om * i1.y + eff * gwi[d0 + 5];
        v[6] = om * i1.z + eff * gwi[d0 + 6];
        v[7] = om * i1.w + eff * gwi[d0 + 7];
        sum = 0.0f; sq = 0.0f;
        #pragma unroll
        for (int i = 0; i < 8; i++) { sum += v[i]; sq = fmaf(v[i], v[i], sq); }
        sum += __shfl_xor_sync(0xffffffffu, sum, 4); sq += __shfl_xor_sync(0xffffffffu, sq, 4);
        sum += __shfl_xor_sync(0xffffffffu, sum, 2); sq += __shfl_xor_sync(0xffffffffu, sq, 2);
        sum += __shfl_xor_sync(0xffffffffu, sum, 1); sq += __shfl_xor_sync(0xffffffffu, sq, 1);
        mean = sum * (1.0f / 64.0f);
        var  = sq * (1.0f / 64.0f) - mean * mean;
        rstd = rsqrtf(var + 1e-5f);
        {
            float o1[8];
            #pragma unroll
            for (int i = 0; i < 8; i++)
                o1[i] = fmaf((v[i] - mean) * rstd, gi[d0 + i], bi[d0 + i]);
            float4* dst = (float4*)(out + OFF_NEXT_I + baseSD + row * D_ + d0);
            dst[0] = make_float4(o1[0], o1[1], o1[2], o1[3]);
            dst[1] = make_float4(o1[4], o1[5], o1[6], o1[7]);
        }
    }

    // ---- final read-vector reduction over the 8 warp partials ----
    __syncthreads();
    if (t < 128) {
        const int d = t & 63;
        const float* src = (t < 64) ? &pr[0][0] : &pi_[0][0];
        float s = 0.0f;
        #pragma unroll
        for (int w = 0; w < 8; w++) s += src[w * D_ + d];
        const long long off = ((t < 64) ? OFF_READ_R : OFF_READ_I) + (long long)b * D_ + d;
        out[off] = s;
    }
}

extern "C" void kernel_launch(void* const* d_in, const int* in_sizes, int n_in,
                              void* d_out, int out_size)
{
    const float* gw_r    = (const float*)d_in[0];
    const float* gw_i    = (const float*)d_in[1];
    const float* mem_r   = (const float*)d_in[2];
    const float* mem_i   = (const float*)d_in[3];
    const float* Wg      = (const float*)d_in[4];
    const float* bg      = (const float*)d_in[5];
    const float* Wa      = (const float*)d_in[6];
    const float* ba      = (const float*)d_in[7];
    const float* gamma_r = (const float*)d_in[8];
    const float* beta_r  = (const float*)d_in[9];
    const float* gamma_i = (const float*)d_in[10];
    const float* beta_i  = (const float*)d_in[11];
    float* out = (float*)d_out;

    am_init_kernel<<<1, 1>>>(out);
    am_fused_kernel<<<B_, 256>>>(gw_r, gw_i, mem_r, mem_i, Wg, bg, Wa, ba,
                                 gamma_r, beta_r, gamma_i, beta_i, out);
}

// round 5
// speedup vs baseline: 1.7201x; 1.7201x over previous
#include <cuda_runtime.h>
#include <math.h>

#define B_ 16384
#define S_ 32
#define D_ 64
#define KTOP 3

constexpr int SD = S_ * D_;
constexpr long long OFF_READ_R = 0;
constexpr long long OFF_READ_I = (long long)B_ * D_;
constexpr long long OFF_NEXT_R = 2LL * B_ * D_;
constexpr long long OFF_NEXT_I = OFF_NEXT_R + (long long)B_ * SD;
constexpr long long OFF_ENT    = OFF_NEXT_I + (long long)B_ * SD;

__global__ void am_init_kernel(float* __restrict__ out) {
    out[OFF_ENT] = 0.0f;
}

__device__ __forceinline__ float dot4(float4 a, float4 b) {
    float s = a.x * b.x;
    s = fmaf(a.y, b.y, s);
    s = fmaf(a.z, b.z, s);
    s = fmaf(a.w, b.w, s);
    return s;
}

__global__ __launch_bounds__(256) void am_fused_kernel(
    const float* __restrict__ gw_r,  const float* __restrict__ gw_i,
    const float* __restrict__ mem_r, const float* __restrict__ mem_i,
    const float* __restrict__ Wg,    const float* __restrict__ bg,
    const float* __restrict__ Wa,    const float* __restrict__ ba,
    const float* __restrict__ gamma_r, const float* __restrict__ beta_r,
    const float* __restrict__ gamma_i, const float* __restrict__ beta_i,
    float* __restrict__ out)
{
    __shared__ float gwr[D_], gwi[D_];
    __shared__ float gr[D_], br[D_], gi[D_], bi[D_];
    __shared__ float sim[S_], attn[S_], sparse[S_];
    __shared__ float wlog[8][S_];      // per-warp logit partials
    __shared__ float pr[8][D_];        // per-warp read_r partials
    __shared__ float pi_[8][D_];       // per-warp read_i partials
    __shared__ float s_wg;

    const int t    = threadIdx.x;
    const int b    = blockIdx.x;
    const int warp = t >> 5;
    const int lane = t & 31;
    const int sub  = t & 15;           // column group: cols 4*sub..4*sub+3
    const int rA   = t >> 4;           // row 0..15
    // rB = rA + 16
    const long long baseSD = (long long)b * SD;

    // ---- contiguous vec4 loads: thread owns rows rA and rA+16, 4 cols each ----
    const float4* m4r = (const float4*)(mem_r + baseSD);
    const float4* m4i = (const float4*)(mem_i + baseSD);
    const float4 mrA = m4r[t];
    const float4 mrB = m4r[t + 256];
    const float4 miA = m4i[t];
    const float4 miB = m4i[t + 256];

    // ---- stage small vectors into SMEM (all coalesced) ----
    if (t < 64) {
        gwr[t] = gw_r[(long long)b * D_ + t];
    } else if (t < 128) {
        gwi[t - 64] = gw_i[(long long)b * D_ + (t - 64)];
    } else if (t < 192) {
        const int d = t - 128;
        gr[d] = gamma_r[d];
        gi[d] = gamma_i[d];
    } else {
        const int d = t - 192;
        br[d] = beta_r[d];
        bi[d] = beta_i[d];
    }
    __syncthreads();

    // per-thread gw slices (registers, reused 3x)
    const float4 gwr4 = ((const float4*)gwr)[sub];
    const float4 gwi4 = ((const float4*)gwi)[sub];

    // ---- sim for rows rA, rA+16 : partial dot + 16-lane butterfly ----
    {
        float accA = dot4(mrA, gwr4) + dot4(miA, gwi4);
        float accB = dot4(mrB, gwr4) + dot4(miB, gwi4);
        #pragma unroll
        for (int o = 8; o; o >>= 1) {
            accA += __shfl_xor_sync(0xffffffffu, accA, o);
            accB += __shfl_xor_sync(0xffffffffu, accB, o);
        }
        if (sub == 0) {
            sim[rA]      = accA;
            sim[rA + 16] = accB;
        }
    }

    // ---- logits partials: warp w owns j in [16w, 16w+16), lane l owns s=l ----
    {
        const int j0 = warp * 16;
        float lacc = 0.0f;
        #pragma unroll
        for (int i = 0; i < 16; i++) {
            const int j = j0 + i;
            const float f = (j < 64) ? gwr[j] : gwi[j - 64];   // broadcast LDS
            lacc = fmaf(f, Wa[j * S_ + lane], lacc);           // coalesced LDG
        }
        wlog[warp][lane] = lacc;
    }
    __syncthreads();

    if (warp == 0) {
        // ---- attention softmax over S=32 ----
        const float v = sim[lane];
        float m = v;
        #pragma unroll
        for (int o = 16; o; o >>= 1) m = fmaxf(m, __shfl_xor_sync(0xffffffffu, m, o));
        const float e = __expf(v - m);
        float ssum = e;
        #pragma unroll
        for (int o = 16; o; o >>= 1) ssum += __shfl_xor_sync(0xffffffffu, ssum, o);
        attn[lane] = e / ssum;
    } else if (warp == 1) {
        // ---- write softmax + entropy + top-3 sparse ----
        float v = ba[lane];
        #pragma unroll
        for (int w = 0; w < 8; w++) v += wlog[w][lane];
        float m = v;
        #pragma unroll
        for (int o = 16; o; o >>= 1) m = fmaxf(m, __shfl_xor_sync(0xffffffffu, m, o));
        const float e = __expf(v - m);
        float ssum = e;
        #pragma unroll
        for (int o = 16; o; o >>= 1) ssum += __shfl_xor_sync(0xffffffffu, ssum, o);
        const float w_ = e / ssum;

        float ent = -w_ * __logf(w_ + 1e-10f);
        #pragma unroll
        for (int o = 16; o; o >>= 1) ent += __shfl_xor_sync(0xffffffffu, ent, o);
        if (lane == 0) atomicAdd(out + OFF_ENT, ent * (1.0f / (float)B_));

        float vv = w_;
        float sp = 0.0f;
        float sumTop = 0.0f;
        #pragma unroll
        for (int k = 0; k < KTOP; k++) {
            float mv = vv;
            int   mi = lane;
            #pragma unroll
            for (int o = 16; o; o >>= 1) {
                const float ov = __shfl_xor_sync(0xffffffffu, mv, o);
                const int   oi = __shfl_xor_sync(0xffffffffu, mi, o);
                if (ov > mv || (ov == mv && oi < mi)) { mv = ov; mi = oi; }
            }
            sumTop += mv;
            if (lane == mi) { sp = mv; vv = -INFINITY; }
        }
        sparse[lane] = sp / (sumTop + 1e-6f);
    } else if (warp == 2) {
        // ---- write gate ----
        float acc = 0.0f;
        #pragma unroll
        for (int i = 0; i < 4; i++) {
            const int j = lane + i * 32;
            const float f = (j < 64) ? gwr[j] : gwi[j - 64];
            acc = fmaf(f, Wg[j], acc);
        }
        #pragma unroll
        for (int o = 16; o; o >>= 1) acc += __shfl_xor_sync(0xffffffffu, acc, o);
        if (lane == 0) s_wg = 1.0f / (1.0f + __expf(-(acc + bg[0])));
    }
    __syncthreads();

    // ---- read-vector partials: combine both rows, fold lane halves ----
    {
        const float aA = attn[rA];
        const float aB = attn[rA + 16];
        float vr[4] = { aA*mrA.x + aB*mrB.x, aA*mrA.y + aB*mrB.y,
                        aA*mrA.z + aB*mrB.z, aA*mrA.w + aB*mrB.w };
        float vi[4] = { aA*miA.x + aB*miB.x, aA*miA.y + aB*miB.y,
                        aA*miA.z + aB*miB.z, aA*miA.w + aB*miB.w };
        #pragma unroll
        for (int i = 0; i < 4; i++) {
            vr[i] += __shfl_xor_sync(0xffffffffu, vr[i], 16);
            vi[i] += __shfl_xor_sync(0xffffffffu, vi[i], 16);
        }
        if (lane < 16) {
            ((float4*)&pr[warp][0])[lane]  = make_float4(vr[0], vr[1], vr[2], vr[3]);
            ((float4*)&pi_[warp][0])[lane] = make_float4(vi[0], vi[1], vi[2], vi[3]);
        }
    }

    // ---- memory update + LayerNorm (rows rA and rA+16; real and imag) ----
    {
        const float4 gr4  = ((const float4*)gr)[sub];
        const float4 br4  = ((const float4*)br)[sub];
        const float4 gi4  = ((const float4*)gi)[sub];
        const float4 bi4  = ((const float4*)bi)[sub];
        const float sw    = s_wg;
        const float effA  = sw * sparse[rA];
        const float effB  = sw * sparse[rA + 16];
        const float omA   = 1.0f - effA;
        const float omB   = 1.0f - effB;

        float4* outR = (float4*)(out + OFF_NEXT_R + baseSD);
        float4* outI = (float4*)(out + OFF_NEXT_I + baseSD);

        #pragma unroll
        for (int part = 0; part < 4; part++) {
            // part 0: real rowA | 1: real rowB | 2: imag rowA | 3: imag rowB
            const float4 src = (part == 0) ? mrA : (part == 1) ? mrB
                             : (part == 2) ? miA : miB;
            const float4 g   = (part < 2) ? gwr4 : gwi4;
            const float  eff = (part & 1) ? effB : effA;
            const float  om  = (part & 1) ? omB  : omA;

            float v0 = om * src.x + eff * g.x;
            float v1 = om * src.y + eff * g.y;
            float v2 = om * src.z + eff * g.z;
            float v3 = om * src.w + eff * g.w;

            float sum = v0 + v1 + v2 + v3;
            float sq  = fmaf(v0, v0, fmaf(v1, v1, fmaf(v2, v2, v3 * v3)));
            #pragma unroll
            for (int o = 8; o; o >>= 1) {
                sum += __shfl_xor_sync(0xffffffffu, sum, o);
                sq  += __shfl_xor_sync(0xffffffffu, sq, o);
            }
            const float mean = sum * (1.0f / 64.0f);
            const float var  = sq * (1.0f / 64.0f) - mean * mean;
            const float rstd = rsqrtf(var + 1e-5f);

            const float4 gam = (part < 2) ? gr4 : gi4;
            const float4 bet = (part < 2) ? br4 : bi4;
            float4 o4;
            o4.x = fmaf((v0 - mean) * rstd, gam.x, bet.x);
            o4.y = fmaf((v1 - mean) * rstd, gam.y, bet.y);
            o4.z = fmaf((v2 - mean) * rstd, gam.z, bet.z);
            o4.w = fmaf((v3 - mean) * rstd, gam.w, bet.w);

            float4* dst = (part < 2) ? outR : outI;
            const int idx = (part & 1) ? (t + 256) : t;
            dst[idx] = o4;
        }
    }

    // ---- final read-vector reduction ----
    __syncthreads();
    if (t < 128) {
        const int d = t & 63;
        const float* src = (t < 64) ? &pr[0][0] : &pi_[0][0];
        float s = 0.0f;
        #pragma unroll
        for (int w = 0; w < 8; w++) s += src[w * D_ + d];
        const long long off = ((t < 64) ? OFF_READ_R : OFF_READ_I) + (long long)b * D_ + d;
        out[off] = s;
    }
}

extern "C" void kernel_launch(void* const* d_in, const int* in_sizes, int n_in,
                              void* d_out, int out_size)
{
    const float* gw_r    = (const float*)d_in[0];
    const float* gw_i    = (const float*)d_in[1];
    const float* mem_r   = (const float*)d_in[2];
    const float* mem_i   = (const float*)d_in[3];
    const float* Wg      = (const float*)d_in[4];
    const float* bg      = (const float*)d_in[5];
    const float* Wa      = (const float*)d_in[6];
    const float* ba      = (const float*)d_in[7];
    const float* gamma_r = (const float*)d_in[8];
    const float* beta_r  = (const float*)d_in[9];
    const float* gamma_i = (const float*)d_in[10];
    const float* beta_i  = (const float*)d_in[11];
    float* out = (float*)d_out;

    am_init_kernel<<<1, 1>>>(out);
    am_fused_kernel<<<B_, 256>>>(gw_r, gw_i, mem_r, mem_i, Wg, bg, Wa, ba,
                                 gamma_r, beta_r, gamma_i, beta_i, out);
}